// round 13
// baseline (speedup 1.0000x reference)
#include <cuda_runtime.h>
#include <cuda_fp16.h>
#include <cuda_bf16.h>
#include <cstdint>

#define N_NODESC 100000
#define N_EDGESC 1600000
#define N_GRAPHS 2048
#define VOCABC   1000
#define HID      64
#define N_CL     2
#define SCAN_B   1024
#define NB_N     ((N_NODESC + SCAN_B - 1) / SCAN_B)   // 98
#define NB_G     ((N_GRAPHS + SCAN_B - 1) / SCAN_B)   // 2
#define VB       ((VOCABC + 7) / 8)                   // vocab blocks (8 rows/block)

// ---------------- scratch (device globals; referenced ONLY from device code) -
__device__ int            g_degi[N_NODESC];
__device__ int            g_incl[N_NODESC];    // inclusive scan of deg (CSR row ends)
__device__ int            g_cursor[N_NODESC];  // exclusive prefix (read-only in fill)
__device__ unsigned short g_rank[N_EDGESC];    // edge rank within its target group
__device__ int            g_gcnt[N_GRAPHS];
__device__ int            g_gincl[N_GRAPHS];
__device__ int            g_bsum[NB_N + NB_G];
__device__ int            g_arrive;
__device__ float          g_dinv[N_NODESC];
__device__ int            g_csr[N_EDGESC];     // source node per CSR slot
__device__ float          g_tv[VOCABC * HID];  // emb @ W1 (fp32 vocab table)
__device__ __half         g_ts [(size_t)N_NODESC * HID];  // layer-1 messages (fp16)
__device__ __half         g_ts2[(size_t)N_NODESC * HID];  // layer-2 messages (fp16)
__device__ float          g_sums[(size_t)N_GRAPHS * HID]; // pooled sums

// ---------------- zero scratch ----------------------------------------------
__global__ void k_zero(int N) {
    int i = blockIdx.x * blockDim.x + threadIdx.x;
    if (i < N) g_degi[i] = 0;
    if (i < N_GRAPHS) g_gcnt[i] = 0;
    if (i < N_GRAPHS * HID) g_sums[i] = 0.f;
    if (i == 0) g_arrive = 0;
}

// ---------------- fused: counts (+edge ranks) + vocab GEMM -------------------
__global__ void k_count_vocab(const int* __restrict__ col,
                              const int* __restrict__ batch,
                              const float* __restrict__ emb,
                              const float* __restrict__ W, int E, int N, int V) {
    __shared__ float sW[HID * HID];
    if (blockIdx.x < VB) {
        int tid = threadIdx.x;
        for (int i = tid; i < HID * HID; i += blockDim.x) sW[i] = W[i];
        __syncthreads();
        int lane = tid & 31, warp = tid >> 5;
        int r = blockIdx.x * 8 + warp;
        if (r >= V) return;
        const float* e = emb + (size_t)r * HID;
        float e_lo = e[lane], e_hi = e[lane + 32];
        float a0 = 0.f, a1 = 0.f;
        #pragma unroll
        for (int k = 0; k < 32; k++) {
            float ek = __shfl_sync(0xffffffffu, e_lo, k);
            a0 = fmaf(ek, sW[k * HID + lane],      a0);
            a1 = fmaf(ek, sW[k * HID + 32 + lane], a1);
        }
        #pragma unroll
        for (int k = 0; k < 32; k++) {
            float ek = __shfl_sync(0xffffffffu, e_hi, k);
            a0 = fmaf(ek, sW[(k + 32) * HID + lane],      a0);
            a1 = fmaf(ek, sW[(k + 32) * HID + 32 + lane], a1);
        }
        g_tv[(size_t)r * HID + lane]      = a0;
        g_tv[(size_t)r * HID + 32 + lane] = a1;
    } else {
        int i = (blockIdx.x - VB) * blockDim.x + threadIdx.x;
        if (i < E) {
            int r = atomicAdd(&g_degi[col[i]], 1);
            g_rank[i] = (unsigned short)r;
        } else if (i < E + N) {
            atomicAdd(&g_gcnt[batch[i - E]], 1);
        }
    }
}

// ---------------- one-launch dual scan (all blocks wave-1 resident) ----------
__device__ __forceinline__ int warp_incl_scan(int x, int lane) {
    #pragma unroll
    for (int o = 1; o < 32; o <<= 1) {
        int u = __shfl_up_sync(0xffffffffu, x, o);
        if (lane >= o) x += u;
    }
    return x;
}

__global__ void k_scan_all(int N) {
    __shared__ int wsum[32];
    __shared__ int spre;
    int t = threadIdx.x, lane = t & 31, w = t >> 5;
    bool isDeg = blockIdx.x < NB_N;
    int lo  = isDeg ? 0 : NB_N;
    int n   = isDeg ? N : N_GRAPHS;
    int idx = (blockIdx.x - lo) * SCAN_B + t;
    int v   = 0;
    if (idx < n) v = isDeg ? g_degi[idx] : g_gcnt[idx];

    int incl = warp_incl_scan(v, lane);
    if (lane == 31) wsum[w] = incl;
    __syncthreads();
    if (w == 0) wsum[lane] = warp_incl_scan(wsum[lane], lane);
    __syncthreads();
    int blockIncl = incl + (w > 0 ? wsum[w - 1] : 0);
    int blockTot = wsum[31];

    if (t == 0) {
        g_bsum[blockIdx.x] = blockTot;
        __threadfence();
        atomicAdd(&g_arrive, 1);
        while (atomicAdd(&g_arrive, 0) < (int)gridDim.x) { }
    }
    __syncthreads();

    if (w == 0) {
        int pre = 0;
        for (int j = lo + lane; j < (int)blockIdx.x; j += 32) pre += g_bsum[j];
        #pragma unroll
        for (int o = 16; o > 0; o >>= 1) pre += __shfl_down_sync(0xffffffffu, pre, o);
        if (lane == 0) spre = pre;
    }
    __syncthreads();
    int fin = blockIncl + spre;

    if (idx < n) {
        if (isDeg) {
            g_incl[idx]   = fin;
            g_cursor[idx] = fin - v;                 // exclusive prefix
            g_dinv[idx]   = rsqrtf((float)(v + 1));  // +1 self loop
        } else {
            g_gincl[idx] = fin;
        }
    }
}

// ---------------- fused: CSR fill (rank-based, no atomics) + l1 messages -----
__global__ void k_fill_l1(const int* __restrict__ row,
                          const int* __restrict__ col,
                          const int* __restrict__ x, int E, int N) {
    int i = blockIdx.x * blockDim.x + threadIdx.x;
    if (i < E) {
        int c = col[i];
        int slot = g_cursor[c] + (int)g_rank[i];
        g_csr[slot] = row[i];
    } else {
        int gid = i - E;            // 16 lanes per node
        int node = gid >> 4;
        if (node >= N) return;
        int lane = gid & 15;
        float d = g_dinv[node];
        float4 v = reinterpret_cast<const float4*>(g_tv + (size_t)x[node] * HID)[lane];
        __half2 h0 = __floats2half2_rn(v.x * d, v.y * d);
        __half2 h1 = __floats2half2_rn(v.z * d, v.w * d);
        uint2 u;
        u.x = *reinterpret_cast<unsigned int*>(&h0);
        u.y = *reinterpret_cast<unsigned int*>(&h1);
        reinterpret_cast<uint2*>(g_ts)[(size_t)node * 16 + lane] = u;
    }
}

// ---------------- warp CSR gather, fully-predicated MLP=8 (no serial tail) ---
__device__ __forceinline__ float2 csr_gather(const __half2* __restrict__ ts,
                                             int c, int lane) {
    int start = (c == 0) ? 0 : g_incl[c - 1];
    int end = g_incl[c];
    float2 a0 = __half22float2(ts[(size_t)c * 32 + lane]);
    float2 a1 = make_float2(0.f, 0.f);
    for (int e = start; e < end; e += 8) {
        int rem = end - e;                       // >= 1
        int r[8];
        #pragma unroll
        for (int j = 0; j < 8; j++)
            r[j] = g_csr[e + (j < rem ? j : 0)]; // clamped: dup loads hit L1
        float2 v[8];
        #pragma unroll
        for (int j = 0; j < 8; j++)
            v[j] = __half22float2(ts[(size_t)r[j] * 32 + lane]);
        #pragma unroll
        for (int j = 0; j < 8; j += 2) {
            if (j < rem)     { a0.x += v[j].x;     a0.y += v[j].y;     }
            if (j + 1 < rem) { a1.x += v[j + 1].x; a1.y += v[j + 1].y; }
        }
    }
    a0.x += a1.x;
    a0.y += a1.y;
    return a0;
}

// ---------------- fused: layer-1 gather + ReLU + GEMM(W2) -> ts2 (fp16) ------
__global__ void k_gather_mm(const float* __restrict__ b1,
                            const float* __restrict__ W2, int n) {
    __shared__ float  sW[HID * HID];
    __shared__ float4 se[8][32];      // per-warp duplicated-e buffer
    int tid = threadIdx.x;
    for (int i = tid; i < HID * HID; i += blockDim.x) sW[i] = W2[i];
    __syncthreads();
    int lane = tid & 31, warp = tid >> 5, wpb = blockDim.x >> 5;
    float2 bb = reinterpret_cast<const float2*>(b1)[lane];
    const __half2* ts = reinterpret_cast<const __half2*>(g_ts);
    const unsigned long long* wu = reinterpret_cast<const unsigned long long*>(sW);
    const ulonglong2* eu = reinterpret_cast<const ulonglong2*>(&se[warp][0]);
    for (int c = blockIdx.x * wpb + warp; c < n; c += gridDim.x * wpb) {
        float2 s = csr_gather(ts, c, lane);
        float d = g_dinv[c];
        float ex = fmaxf(fmaf(d, s.x, bb.x), 0.f);   // relu(h), col 2*lane
        float ey = fmaxf(fmaf(d, s.y, bb.y), 0.f);   // col 2*lane+1
        __syncwarp();
        se[warp][lane] = make_float4(ex, ex, ey, ey);
        __syncwarp();
        unsigned long long acc = 0ull;               // packed (0.f, 0.f)
        #pragma unroll
        for (int k = 0; k < HID; k += 2) {
            ulonglong2 ee = eu[k >> 1];              // dup(e_k), dup(e_{k+1})
            unsigned long long w0 = wu[k * 32 + lane];
            unsigned long long w1 = wu[(k + 1) * 32 + lane];
            asm("fma.rn.f32x2 %0, %1, %2, %0;" : "+l"(acc) : "l"(ee.x), "l"(w0));
            asm("fma.rn.f32x2 %0, %1, %2, %0;" : "+l"(acc) : "l"(ee.y), "l"(w1));
        }
        float a, bc;
        asm("mov.b64 {%0, %1}, %2;" : "=f"(a), "=f"(bc) : "l"(acc));
        reinterpret_cast<__half2*>(g_ts2)[(size_t)c * 32 + lane] =
            __floats2half2_rn(a * d, bc * d);
    }
}

// ---------------- fused: layer-2 gather + ReLU + pool scatter (persistent) ---
__global__ void k_gather_pool(const int* __restrict__ batch,
                              const float* __restrict__ b2, int n) {
    int lane = threadIdx.x & 31;
    int warp = threadIdx.x >> 5;
    int wpb = blockDim.x >> 5;
    const __half2* ts = reinterpret_cast<const __half2*>(g_ts2);
    for (int c = blockIdx.x * wpb + warp; c < n; c += gridDim.x * wpb) {
        float2 s = csr_gather(ts, c, lane);
        float d = g_dinv[c];
        float2 bb = reinterpret_cast<const float2*>(b2)[lane];
        float hx = fmaxf(fmaf(d, s.x, bb.x), 0.f);
        float hy = fmaxf(fmaf(d, s.y, bb.y), 0.f);
        int g = batch[c];
        float* dst = g_sums + (size_t)g * HID + 2 * lane;
        asm volatile("red.global.add.v2.f32 [%0], {%1,%2};"
                     :: "l"(dst), "f"(hx), "f"(hy) : "memory");
    }
}

// ---------------- head: out[g] = (sums[g]/cnt) @ Wl + bl ---------------------
__global__ void k_head(const float* __restrict__ Wl,
                       const float* __restrict__ bl,
                       float* __restrict__ out) {
    int lane = threadIdx.x & 31;
    int warp = threadIdx.x >> 5;
    int g = blockIdx.x * (blockDim.x >> 5) + warp;
    if (g >= N_GRAPHS) return;
    int start = (g == 0) ? 0 : g_gincl[g - 1];
    int cnt = g_gincl[g] - start;
    float inv = 1.0f / fmaxf((float)cnt, 1.0f);
    float s0 = g_sums[(size_t)g * HID + 2 * lane] * inv;
    float s1 = g_sums[(size_t)g * HID + 2 * lane + 1] * inv;
    float a0 = s0 * Wl[(2 * lane) * N_CL + 0] + s1 * Wl[(2 * lane + 1) * N_CL + 0];
    float a1 = s0 * Wl[(2 * lane) * N_CL + 1] + s1 * Wl[(2 * lane + 1) * N_CL + 1];
    #pragma unroll
    for (int off = 16; off > 0; off >>= 1) {
        a0 += __shfl_down_sync(0xffffffffu, a0, off);
        a1 += __shfl_down_sync(0xffffffffu, a1, off);
    }
    if (lane == 0) {
        out[g * N_CL + 0] = a0 + bl[0];
        out[g * N_CL + 1] = a1 + bl[1];
    }
}

// ---------------- launch ----------------------------------------------------
extern "C" void kernel_launch(void* const* d_in, const int* in_sizes, int n_in,
                              void* d_out, int out_size) {
    const int*   x     = (const int*)  d_in[0];
    const int*   eidx  = (const int*)  d_in[1];
    const int*   batch = (const int*)  d_in[2];
    const float* emb   = (const float*)d_in[3];
    const float* W1    = (const float*)d_in[4];
    const float* b1    = (const float*)d_in[5];
    const float* W2    = (const float*)d_in[6];
    const float* b2    = (const float*)d_in[7];
    const float* Wl    = (const float*)d_in[8];
    const float* bl    = (const float*)d_in[9];
    float* out = (float*)d_out;

    const int N = in_sizes[0];
    const int E = in_sizes[1] / 2;
    const int V = in_sizes[3] / HID;
    const int* row = eidx;       // sources
    const int* col = eidx + E;   // targets

    const int T = 256;
    const int ZB = (N_GRAPHS * HID + T - 1) / T;   // covers degi/gcnt/sums
    const int CB = (E + N + T - 1) / T;            // count work

    // zero -> fused count+vocab GEMM -> dual scan -> CSR fill + l1 messages
    k_zero       <<<ZB, T>>>(N);
    k_count_vocab<<<VB + CB, T>>>(col, batch, emb, W1, E, N, V);
    k_scan_all   <<<NB_N + NB_G, SCAN_B>>>(N);
    k_fill_l1    <<<(E + 16 * N + T - 1) / T, T>>>(row, col, x, E, N);

    // layer 1 gather + GEMM(W2) fused  -> ts2  (single persistent wave)
    k_gather_mm<<<1184, 256>>>(b1, W2, N);

    // layer 2 gather + pool scatter fused (persistent)
    k_gather_pool<<<1184, 256>>>(batch, b2, N);

    // head
    k_head<<<(N_GRAPHS + 7) / 8, 256>>>(Wl, bl, out);
}

// round 14
// speedup vs baseline: 1.1396x; 1.1396x over previous
#include <cuda_runtime.h>
#include <cuda_fp16.h>
#include <cuda_bf16.h>
#include <cstdint>

#define N_NODESC 100000
#define N_EDGESC 1600000
#define N_GRAPHS 2048
#define VOCABC   1000
#define HID      64
#define N_CL     2
#define SCAN_B   1024
#define NB_N     ((N_NODESC + SCAN_B - 1) / SCAN_B)   // 98
#define NB_G     ((N_GRAPHS + SCAN_B - 1) / SCAN_B)   // 2
#define VB       ((VOCABC + 7) / 8)                   // vocab blocks (8 rows/block)
#define POOL_G   1184                                  // 148 SMs x 8 blocks... (persistent wave)

// ---------------- scratch (device globals; referenced ONLY from device code) -
__device__ int            g_degi[N_NODESC];
__device__ int            g_incl[N_NODESC];    // inclusive scan of deg (CSR row ends)
__device__ int            g_cursor[N_NODESC];  // exclusive prefix (read-only in fill)
__device__ unsigned short g_rank[N_EDGESC];    // edge rank within its target group
__device__ int            g_gcnt[N_GRAPHS];
__device__ int            g_gincl[N_GRAPHS];
__device__ int            g_bsum[NB_N + NB_G];
__device__ int            g_arrive;
__device__ int            g_arrive2;
__device__ float          g_dinv[N_NODESC];
__device__ int            g_csr[N_EDGESC];     // source node per CSR slot
__device__ float          g_tv[VOCABC * HID];  // emb @ W1 (fp32 vocab table)
__device__ __half         g_ts [(size_t)N_NODESC * HID];  // layer-1 messages (fp16)
__device__ __half         g_ts2[(size_t)N_NODESC * HID];  // layer-2 messages (fp16)
__device__ float          g_sums[(size_t)N_GRAPHS * HID]; // pooled sums

// ---------------- zero scratch ----------------------------------------------
__global__ void k_zero(int N) {
    int i = blockIdx.x * blockDim.x + threadIdx.x;
    if (i < N) g_degi[i] = 0;
    if (i < N_GRAPHS) g_gcnt[i] = 0;
    if (i < N_GRAPHS * HID) g_sums[i] = 0.f;
    if (i == 0) { g_arrive = 0; g_arrive2 = 0; }
}

// ---------------- fused: counts (+edge ranks) + vocab GEMM -------------------
__global__ void k_count_vocab(const int* __restrict__ col,
                              const int* __restrict__ batch,
                              const float* __restrict__ emb,
                              const float* __restrict__ W, int E, int N, int V) {
    __shared__ float sW[HID * HID];
    if (blockIdx.x < VB) {
        int tid = threadIdx.x;
        for (int i = tid; i < HID * HID; i += blockDim.x) sW[i] = W[i];
        __syncthreads();
        int lane = tid & 31, warp = tid >> 5;
        int r = blockIdx.x * 8 + warp;
        if (r >= V) return;
        const float* e = emb + (size_t)r * HID;
        float e_lo = e[lane], e_hi = e[lane + 32];
        float a0 = 0.f, a1 = 0.f;
        #pragma unroll
        for (int k = 0; k < 32; k++) {
            float ek = __shfl_sync(0xffffffffu, e_lo, k);
            a0 = fmaf(ek, sW[k * HID + lane],      a0);
            a1 = fmaf(ek, sW[k * HID + 32 + lane], a1);
        }
        #pragma unroll
        for (int k = 0; k < 32; k++) {
            float ek = __shfl_sync(0xffffffffu, e_hi, k);
            a0 = fmaf(ek, sW[(k + 32) * HID + lane],      a0);
            a1 = fmaf(ek, sW[(k + 32) * HID + 32 + lane], a1);
        }
        g_tv[(size_t)r * HID + lane]      = a0;
        g_tv[(size_t)r * HID + 32 + lane] = a1;
    } else {
        int i = (blockIdx.x - VB) * blockDim.x + threadIdx.x;
        if (i < E) {
            int r = atomicAdd(&g_degi[col[i]], 1);
            g_rank[i] = (unsigned short)r;
        } else if (i < E + N) {
            atomicAdd(&g_gcnt[batch[i - E]], 1);
        }
    }
}

// ---------------- one-launch dual scan (all blocks wave-1 resident) ----------
__device__ __forceinline__ int warp_incl_scan(int x, int lane) {
    #pragma unroll
    for (int o = 1; o < 32; o <<= 1) {
        int u = __shfl_up_sync(0xffffffffu, x, o);
        if (lane >= o) x += u;
    }
    return x;
}

__global__ void k_scan_all(int N) {
    __shared__ int wsum[32];
    __shared__ int spre;
    int t = threadIdx.x, lane = t & 31, w = t >> 5;
    bool isDeg = blockIdx.x < NB_N;
    int lo  = isDeg ? 0 : NB_N;
    int n   = isDeg ? N : N_GRAPHS;
    int idx = (blockIdx.x - lo) * SCAN_B + t;
    int v   = 0;
    if (idx < n) v = isDeg ? g_degi[idx] : g_gcnt[idx];

    int incl = warp_incl_scan(v, lane);
    if (lane == 31) wsum[w] = incl;
    __syncthreads();
    if (w == 0) wsum[lane] = warp_incl_scan(wsum[lane], lane);
    __syncthreads();
    int blockIncl = incl + (w > 0 ? wsum[w - 1] : 0);
    int blockTot = wsum[31];

    if (t == 0) {
        g_bsum[blockIdx.x] = blockTot;
        __threadfence();
        atomicAdd(&g_arrive, 1);
        while (atomicAdd(&g_arrive, 0) < (int)gridDim.x) { }
    }
    __syncthreads();

    if (w == 0) {
        int pre = 0;
        for (int j = lo + lane; j < (int)blockIdx.x; j += 32) pre += g_bsum[j];
        #pragma unroll
        for (int o = 16; o > 0; o >>= 1) pre += __shfl_down_sync(0xffffffffu, pre, o);
        if (lane == 0) spre = pre;
    }
    __syncthreads();
    int fin = blockIncl + spre;

    if (idx < n) {
        if (isDeg) {
            g_incl[idx]   = fin;
            g_cursor[idx] = fin - v;                 // exclusive prefix
            g_dinv[idx]   = rsqrtf((float)(v + 1));  // +1 self loop
        } else {
            g_gincl[idx] = fin;
        }
    }
}

// ---------------- fused: CSR fill (rank-based, no atomics) + l1 messages -----
__global__ void k_fill_l1(const int* __restrict__ row,
                          const int* __restrict__ col,
                          const int* __restrict__ x, int E, int N) {
    int i = blockIdx.x * blockDim.x + threadIdx.x;
    if (i < E) {
        int c = col[i];
        int slot = g_cursor[c] + (int)g_rank[i];
        g_csr[slot] = row[i];
    } else {
        int gid = i - E;            // 16 lanes per node
        int node = gid >> 4;
        if (node >= N) return;
        int lane = gid & 15;
        float d = g_dinv[node];
        float4 v = reinterpret_cast<const float4*>(g_tv + (size_t)x[node] * HID)[lane];
        __half2 h0 = __floats2half2_rn(v.x * d, v.y * d);
        __half2 h1 = __floats2half2_rn(v.z * d, v.w * d);
        uint2 u;
        u.x = *reinterpret_cast<unsigned int*>(&h0);
        u.y = *reinterpret_cast<unsigned int*>(&h1);
        reinterpret_cast<uint2*>(g_ts)[(size_t)node * 16 + lane] = u;
    }
}

// ---------------- warp CSR gather, MLP=8 (R11-validated shape) ---------------
__device__ __forceinline__ float2 csr_gather(const __half2* __restrict__ ts,
                                             int c, int lane) {
    int start = (c == 0) ? 0 : g_incl[c - 1];
    int end = g_incl[c];
    float2 a0 = __half22float2(ts[(size_t)c * 32 + lane]);
    float2 a1 = make_float2(0.f, 0.f);
    int e = start;
    while (e + 8 <= end) {
        int r[8];
        #pragma unroll
        for (int j = 0; j < 8; j++) r[j] = g_csr[e + j];
        float2 v[8];
        #pragma unroll
        for (int j = 0; j < 8; j++) v[j] = __half22float2(ts[(size_t)r[j] * 32 + lane]);
        #pragma unroll
        for (int j = 0; j < 8; j += 2) {
            a0.x += v[j].x;     a0.y += v[j].y;
            a1.x += v[j + 1].x; a1.y += v[j + 1].y;
        }
        e += 8;
    }
    if (e + 4 <= end) {
        int r[4];
        #pragma unroll
        for (int j = 0; j < 4; j++) r[j] = g_csr[e + j];
        float2 v[4];
        #pragma unroll
        for (int j = 0; j < 4; j++) v[j] = __half22float2(ts[(size_t)r[j] * 32 + lane]);
        a0.x += v[0].x + v[2].x; a0.y += v[0].y + v[2].y;
        a1.x += v[1].x + v[3].x; a1.y += v[1].y + v[3].y;
        e += 4;
    }
    for (; e < end; e++) {
        int r = g_csr[e];
        float2 v = __half22float2(ts[(size_t)r * 32 + lane]);
        a0.x += v.x; a0.y += v.y;
    }
    a0.x += a1.x;
    a0.y += a1.y;
    return a0;
}

// ---------------- fused: layer-1 gather + ReLU + GEMM(W2) -> ts2 (fp16) ------
__global__ void k_gather_mm(const float* __restrict__ b1,
                            const float* __restrict__ W2, int n) {
    __shared__ float  sW[HID * HID];
    __shared__ float4 se[8][32];      // per-warp duplicated-e buffer
    int tid = threadIdx.x;
    for (int i = tid; i < HID * HID; i += blockDim.x) sW[i] = W2[i];
    __syncthreads();
    int lane = tid & 31, warp = tid >> 5, wpb = blockDim.x >> 5;
    float2 bb = reinterpret_cast<const float2*>(b1)[lane];
    const __half2* ts = reinterpret_cast<const __half2*>(g_ts);
    const unsigned long long* wu = reinterpret_cast<const unsigned long long*>(sW);
    const ulonglong2* eu = reinterpret_cast<const ulonglong2*>(&se[warp][0]);
    for (int c = blockIdx.x * wpb + warp; c < n; c += gridDim.x * wpb) {
        float2 s = csr_gather(ts, c, lane);
        float d = g_dinv[c];
        float ex = fmaxf(fmaf(d, s.x, bb.x), 0.f);   // relu(h), col 2*lane
        float ey = fmaxf(fmaf(d, s.y, bb.y), 0.f);   // col 2*lane+1
        __syncwarp();
        se[warp][lane] = make_float4(ex, ex, ey, ey);
        __syncwarp();
        unsigned long long acc = 0ull;               // packed (0.f, 0.f)
        #pragma unroll
        for (int k = 0; k < HID; k += 2) {
            ulonglong2 ee = eu[k >> 1];              // dup(e_k), dup(e_{k+1})
            unsigned long long w0 = wu[k * 32 + lane];
            unsigned long long w1 = wu[(k + 1) * 32 + lane];
            asm("fma.rn.f32x2 %0, %1, %2, %0;" : "+l"(acc) : "l"(ee.x), "l"(w0));
            asm("fma.rn.f32x2 %0, %1, %2, %0;" : "+l"(acc) : "l"(ee.y), "l"(w1));
        }
        float a, bc;
        asm("mov.b64 {%0, %1}, %2;" : "=f"(a), "=f"(bc) : "l"(acc));
        reinterpret_cast<__half2*>(g_ts2)[(size_t)c * 32 + lane] =
            __floats2half2_rn(a * d, bc * d);
    }
}

// ---------------- layer-2 gather (half-warp per node) + pool + fused head ----
// 16 lanes x uint2 (8 B) cover one 128 B message row; a warp serves 2 nodes.
__global__ void k_gather_pool(const int* __restrict__ batch,
                              const float* __restrict__ b2,
                              const float* __restrict__ Wl,
                              const float* __restrict__ bl,
                              float* __restrict__ out, int n) {
    int lane = threadIdx.x & 31;
    int warp = threadIdx.x >> 5;
    int wpb = blockDim.x >> 5;
    int hl = lane & 15;               // half-lane
    int side = lane >> 4;             // 0 or 1
    const uint2* ts = reinterpret_cast<const uint2*>(g_ts2);
    int npairs = (n + 1) >> 1;
    for (int p = blockIdx.x * wpb + warp; p < npairs; p += gridDim.x * wpb) {
        int c = 2 * p + side;
        if (c < n) {
            int start = (c == 0) ? 0 : g_incl[c - 1];
            int end = g_incl[c];
            // self message
            uint2 u = ts[(size_t)c * 16 + hl];
            float2 f0 = __half22float2(*reinterpret_cast<__half2*>(&u.x));
            float2 f1 = __half22float2(*reinterpret_cast<__half2*>(&u.y));
            float4 a = make_float4(f0.x, f0.y, f1.x, f1.y);
            int e = start;
            while (e + 8 <= end) {
                int r[8];
                #pragma unroll
                for (int j = 0; j < 8; j++) r[j] = g_csr[e + j];
                uint2 v[8];
                #pragma unroll
                for (int j = 0; j < 8; j++) v[j] = ts[(size_t)r[j] * 16 + hl];
                #pragma unroll
                for (int j = 0; j < 8; j++) {
                    float2 g0 = __half22float2(*reinterpret_cast<__half2*>(&v[j].x));
                    float2 g1 = __half22float2(*reinterpret_cast<__half2*>(&v[j].y));
                    a.x += g0.x; a.y += g0.y; a.z += g1.x; a.w += g1.y;
                }
                e += 8;
            }
            if (e + 4 <= end) {
                int r[4];
                #pragma unroll
                for (int j = 0; j < 4; j++) r[j] = g_csr[e + j];
                uint2 v[4];
                #pragma unroll
                for (int j = 0; j < 4; j++) v[j] = ts[(size_t)r[j] * 16 + hl];
                #pragma unroll
                for (int j = 0; j < 4; j++) {
                    float2 g0 = __half22float2(*reinterpret_cast<__half2*>(&v[j].x));
                    float2 g1 = __half22float2(*reinterpret_cast<__half2*>(&v[j].y));
                    a.x += g0.x; a.y += g0.y; a.z += g1.x; a.w += g1.y;
                }
                e += 4;
            }
            for (; e < end; e++) {
                int r = g_csr[e];
                uint2 v = ts[(size_t)r * 16 + hl];
                float2 g0 = __half22float2(*reinterpret_cast<__half2*>(&v.x));
                float2 g1 = __half22float2(*reinterpret_cast<__half2*>(&v.y));
                a.x += g0.x; a.y += g0.y; a.z += g1.x; a.w += g1.y;
            }
            float d = g_dinv[c];
            float4 bb = reinterpret_cast<const float4*>(b2)[hl];
            float hx = fmaxf(fmaf(d, a.x, bb.x), 0.f);
            float hy = fmaxf(fmaf(d, a.y, bb.y), 0.f);
            float hz = fmaxf(fmaf(d, a.z, bb.z), 0.f);
            float hw = fmaxf(fmaf(d, a.w, bb.w), 0.f);
            int g = batch[c];
            float* dst = g_sums + (size_t)g * HID + hl * 4;
            asm volatile("red.global.add.v4.f32 [%0], {%1,%2,%3,%4};"
                         :: "l"(dst), "f"(hx), "f"(hy), "f"(hz), "f"(hw) : "memory");
        }
    }

    // ---- grid-wide arrive, then fused head (single persistent wave) ----
    __threadfence();
    __syncthreads();
    if (threadIdx.x == 0) {
        atomicAdd(&g_arrive2, 1);
        while (atomicAdd(&g_arrive2, 0) < (int)gridDim.x) { }
    }
    __syncthreads();

    int g = blockIdx.x * wpb + warp;
    if (g >= N_GRAPHS) return;
    int start = (g == 0) ? 0 : g_gincl[g - 1];
    int cnt = g_gincl[g] - start;
    float inv = 1.0f / fmaxf((float)cnt, 1.0f);
    float s0 = g_sums[(size_t)g * HID + 2 * lane] * inv;
    float s1 = g_sums[(size_t)g * HID + 2 * lane + 1] * inv;
    float a0 = s0 * Wl[(2 * lane) * N_CL + 0] + s1 * Wl[(2 * lane + 1) * N_CL + 0];
    float a1 = s0 * Wl[(2 * lane) * N_CL + 1] + s1 * Wl[(2 * lane + 1) * N_CL + 1];
    #pragma unroll
    for (int off = 16; off > 0; off >>= 1) {
        a0 += __shfl_down_sync(0xffffffffu, a0, off);
        a1 += __shfl_down_sync(0xffffffffu, a1, off);
    }
    if (lane == 0) {
        out[g * N_CL + 0] = a0 + bl[0];
        out[g * N_CL + 1] = a1 + bl[1];
    }
}

// ---------------- launch ----------------------------------------------------
extern "C" void kernel_launch(void* const* d_in, const int* in_sizes, int n_in,
                              void* d_out, int out_size) {
    const int*   x     = (const int*)  d_in[0];
    const int*   eidx  = (const int*)  d_in[1];
    const int*   batch = (const int*)  d_in[2];
    const float* emb   = (const float*)d_in[3];
    const float* W1    = (const float*)d_in[4];
    const float* b1    = (const float*)d_in[5];
    const float* W2    = (const float*)d_in[6];
    const float* b2    = (const float*)d_in[7];
    const float* Wl    = (const float*)d_in[8];
    const float* bl    = (const float*)d_in[9];
    float* out = (float*)d_out;

    const int N = in_sizes[0];
    const int E = in_sizes[1] / 2;
    const int V = in_sizes[3] / HID;
    const int* row = eidx;       // sources
    const int* col = eidx + E;   // targets

    const int T = 256;
    const int ZB = (N_GRAPHS * HID + T - 1) / T;   // covers degi/gcnt/sums
    const int CB = (E + N + T - 1) / T;            // count work

    // zero -> fused count+vocab GEMM -> dual scan -> CSR fill + l1 messages
    k_zero       <<<ZB, T>>>(N);
    k_count_vocab<<<VB + CB, T>>>(col, batch, emb, W1, E, N, V);
    k_scan_all   <<<NB_N + NB_G, SCAN_B>>>(N);
    k_fill_l1    <<<(E + 16 * N + T - 1) / T, T>>>(row, col, x, E, N);

    // layer 1 gather + GEMM(W2) fused  -> ts2  (single persistent wave)
    k_gather_mm<<<1184, 256>>>(b1, W2, N);

    // layer 2 gather (half-warp/node) + pool + head (single persistent wave)
    k_gather_pool<<<POOL_G, 256>>>(batch, b2, Wl, bl, out, N);
}